// round 10
// baseline (speedup 1.0000x reference)
#include <cuda_runtime.h>

#define NN 50000
#define NE 800000
#define ET (NE + NN)        // 850000 edges incl. self loops
#define D 64
#define H 6
#define HD 384
#define BATCH 1024

// ---------------- scratch (device globals; no allocations allowed) ----------
__device__ float g_xp[(size_t)NN * HD];     // transformed feats; reused as x2^T at the end
__device__ float g_y[(size_t)ET * 64];      // per-edge head-reduced messages (218MB)
__device__ float g_as[NN * H];
__device__ float g_ad[NN * H];
__device__ float g_s[NN * H];               // softmax sums -> (1/6)/(s+eps)
__device__ float g_x1[NN * D];
__device__ float g_x2[NN * D];
__device__ int   g_srcptr[NN + 1];
__device__ int   g_dstptr[NN + 1];
__device__ int   g_cur1[NN];
__device__ int   g_cur2[NN];
__device__ int   g_sdst[ET];                // dst per edge, src-CSR order
__device__ int   g_pos[ET];                 // original edge id -> src-CSR slot
__device__ int   g_edpos[ET];               // dst-CSR order -> src-CSR slot
__device__ float g_pool[BATCH * D];
__device__ float g_wad[64 * 12];            // folded attention weights

// ---------------- mma.sync tf32 helpers (frag layout verified in R6) ---------
__device__ __forceinline__ unsigned f2tf(float x) {
    unsigned r; asm("cvt.rna.tf32.f32 %0, %1;" : "=r"(r) : "f"(x)); return r;
}
__device__ __forceinline__ void mma_tf32(float* c, unsigned a0, unsigned a1,
                                         unsigned a2, unsigned a3,
                                         unsigned b0, unsigned b1) {
    asm volatile(
        "mma.sync.aligned.m16n8k8.row.col.f32.tf32.tf32.f32 "
        "{%0,%1,%2,%3}, {%4,%5,%6,%7}, {%8,%9}, {%0,%1,%2,%3};"
        : "+f"(c[0]), "+f"(c[1]), "+f"(c[2]), "+f"(c[3])
        : "r"(a0), "r"(a1), "r"(a2), "r"(a3), "r"(b0), "r"(b1));
}

// ---------------- CSR build (both orientations) ------------------------------
__global__ void k_init2() {
    int i = blockIdx.x * blockDim.x + threadIdx.x;
    if (i < NN) { g_cur1[i] = 1; g_cur2[i] = 1; }     // self loop in both
}

__global__ void k_count2(const int* __restrict__ ei) {
    int e = blockIdx.x * blockDim.x + threadIdx.x;
    if (e < NE) {
        atomicAdd(&g_cur1[ei[e]], 1);          // by src
        atomicAdd(&g_cur2[ei[NE + e]], 1);     // by dst
    }
}

// grid=2: block 0 scans cur1->srcptr, block 1 scans cur2->dstptr
__global__ void __launch_bounds__(1024) k_scan2() {
    __shared__ int wsum[32];
    int* cnt = blockIdx.x ? g_cur2 : g_cur1;
    int* ptr = blockIdx.x ? g_dstptr : g_srcptr;
    int tid = threadIdx.x;
    int lane = tid & 31, warp = tid >> 5;
    int base = tid * 49;
    int s = 0;
    for (int i = 0; i < 49; i++) {
        int idx = base + i;
        if (idx < NN) s += cnt[idx];
    }
    int x = s;
#pragma unroll
    for (int off = 1; off < 32; off <<= 1) {
        int y = __shfl_up_sync(0xffffffffu, x, off);
        if (lane >= off) x += y;
    }
    if (lane == 31) wsum[warp] = x;
    __syncthreads();
    if (warp == 0) {
        int w = wsum[lane];
#pragma unroll
        for (int off = 1; off < 32; off <<= 1) {
            int y = __shfl_up_sync(0xffffffffu, w, off);
            if (lane >= off) w += y;
        }
        wsum[lane] = w;
    }
    __syncthreads();
    int tbase = x - s + (warp ? wsum[warp - 1] : 0);
    int run = tbase;
    for (int i = 0; i < 49; i++) {
        int idx = base + i;
        if (idx < NN) {
            int v = cnt[idx];
            ptr[idx] = run;
            cnt[idx] = run;      // becomes cursor for scatter
            run += v;
        }
    }
    if (tid == 1023) ptr[NN] = tbase + s;   // == ET
}

__global__ void k_scat_src(const int* __restrict__ ei) {
    int i = blockIdx.x * blockDim.x + threadIdx.x;
    if (i >= ET) return;
    int s, d;
    if (i < NE) { s = ei[i]; d = ei[NE + i]; }
    else        { s = i - NE; d = s; }
    int pos = atomicAdd(&g_cur1[s], 1);
    g_sdst[pos] = d;
    g_pos[i] = pos;
}

__global__ void k_scat_dst(const int* __restrict__ ei) {
    int i = blockIdx.x * blockDim.x + threadIdx.x;
    if (i >= ET) return;
    int d = (i < NE) ? ei[NE + i] : (i - NE);
    int p2 = atomicAdd(&g_cur2[d], 1);
    g_edpos[p2] = g_pos[i];
}

// ---------------- xp = x @ W via mma.sync (3xTF32) ---------------------------
__global__ void __launch_bounds__(256) k_gemm_mma(const float* __restrict__ x0,
                                                  const float* __restrict__ W, int layer) {
    const float* __restrict__ x = (layer == 0) ? x0 : g_x1;
    int t = threadIdx.x;
    int wid = t >> 5, lane = t & 31;
    int r = lane >> 2, c = lane & 3;
    int mg = wid >> 2;
    int noff = (wid & 3) * 96;
    int m0 = blockIdx.x * 32 + mg * 16;
    int rowA = m0 + r;
    bool vA = rowA < NN, vB = (rowA + 8) < NN;

    float acc[12][4];
#pragma unroll
    for (int nt = 0; nt < 12; nt++)
#pragma unroll
        for (int i = 0; i < 4; i++) acc[nt][i] = 0.f;

    const float* pA0 = x + (size_t)rowA * 64;
    const float* pA1 = x + (size_t)(rowA + 8) * 64;
    int nlane = noff + r;

#pragma unroll
    for (int k8 = 0; k8 < 8; k8++) {
        int kc = k8 * 8 + c;
        float a00 = vA ? pA0[kc]     : 0.f;
        float a01 = vB ? pA1[kc]     : 0.f;
        float a02 = vA ? pA0[kc + 4] : 0.f;
        float a03 = vB ? pA1[kc + 4] : 0.f;
        unsigned ah0 = f2tf(a00), ah1 = f2tf(a01), ah2 = f2tf(a02), ah3 = f2tf(a03);
        unsigned al0 = f2tf(a00 - __uint_as_float(ah0));
        unsigned al1 = f2tf(a01 - __uint_as_float(ah1));
        unsigned al2 = f2tf(a02 - __uint_as_float(ah2));
        unsigned al3 = f2tf(a03 - __uint_as_float(ah3));

        const float* w0p = W + (size_t)kc * HD + nlane;
        const float* w1p = W + (size_t)(kc + 4) * HD + nlane;
#pragma unroll
        for (int nt = 0; nt < 12; nt++) {
            float b0r = w0p[nt * 8];
            float b1r = w1p[nt * 8];
            unsigned bh0 = f2tf(b0r), bh1 = f2tf(b1r);
            unsigned bl0 = f2tf(b0r - __uint_as_float(bh0));
            unsigned bl1 = f2tf(b1r - __uint_as_float(bh1));
            mma_tf32(acc[nt], ah0, ah1, ah2, ah3, bh0, bh1);
            mma_tf32(acc[nt], ah0, ah1, ah2, ah3, bl0, bl1);
            mma_tf32(acc[nt], al0, al1, al2, al3, bh0, bh1);
        }
    }
#pragma unroll
    for (int nt = 0; nt < 12; nt++) {
        int n0 = noff + nt * 8 + 2 * c;
        if (vA) *(float2*)&g_xp[(size_t)rowA * HD + n0] = make_float2(acc[nt][0], acc[nt][1]);
        if (vB) *(float2*)&g_xp[(size_t)(rowA + 8) * HD + n0] = make_float2(acc[nt][2], acc[nt][3]);
    }
}

// ---------------- folded attention weights -----------------------------------
__global__ void __launch_bounds__(384) k_prew(const float* __restrict__ W,
                                              const float* __restrict__ asrc,
                                              const float* __restrict__ adst) {
    int t = threadIdx.x;
    int k = t % 64, h = t / 64;
    float sa = 0.f, sd = 0.f;
    const float* wr = W + (size_t)k * HD + h * 64;
#pragma unroll 8
    for (int d = 0; d < 64; d++) {
        float wv = wr[d];
        sa += wv * asrc[h * 64 + d];
        sd += wv * adst[h * 64 + d];
    }
    g_wad[k * 12 + h]     = sa;
    g_wad[k * 12 + 6 + h] = sd;
}

// ---------------- as/ad = x @ wad --------------------------------------------
__global__ void __launch_bounds__(128) k_attn2(const float* __restrict__ x0, int layer) {
    __shared__ float sw[64 * 12];
    const float* __restrict__ x = (layer == 0) ? x0 : g_x1;
    int t = threadIdx.x;
#pragma unroll
    for (int i = t; i < 768; i += 128) sw[i] = g_wad[i];
    __syncthreads();
    int n = blockIdx.x * 128 + t;
    if (n >= NN) return;
    float as[6], ad[6];
#pragma unroll
    for (int h = 0; h < 6; h++) { as[h] = 0.f; ad[h] = 0.f; }
    const float4* xr = (const float4*)(x + (size_t)n * 64);
#pragma unroll
    for (int k4 = 0; k4 < 16; k4++) {
        float4 xv = xr[k4];
        const float* w0 = &sw[(4 * k4) * 12];
#pragma unroll
        for (int h = 0; h < 6; h++) {
            as[h] += xv.x * w0[h]      + xv.y * w0[12 + h]
                   + xv.z * w0[24 + h] + xv.w * w0[36 + h];
            ad[h] += xv.x * w0[6 + h]      + xv.y * w0[18 + h]
                   + xv.z * w0[30 + h] + xv.w * w0[42 + h];
        }
    }
#pragma unroll
    for (int h = 0; h < 6; h++) {
        g_as[n * 6 + h] = as[h];
        g_ad[n * 6 + h] = ad[h];
    }
}

// ---------------- softmax denominators (scatter form) ------------------------
__global__ void k_zero_s() {
    int i = blockIdx.x * blockDim.x + threadIdx.x;
    if (i < NN * H) g_s[i] = 0.f;
}

__global__ void __launch_bounds__(256) k_pass1(const int* __restrict__ ei) {
    int i = blockIdx.x * blockDim.x + threadIdx.x;
    if (i >= ET) return;
    int s, d;
    if (i < NE) { s = ei[i]; d = ei[NE + i]; }
    else        { s = i - NE; d = s; }
    const float2* ap = (const float2*)(g_as + s * 6);
    const float2* dp = (const float2*)(g_ad + d * 6);
    float2 a0 = ap[0], a1 = ap[1], a2 = ap[2];
    float2 d0 = dp[0], d1 = dp[1], d2 = dp[2];
    float v[6] = { a0.x + d0.x, a0.y + d0.y, a1.x + d1.x,
                   a1.y + d1.y, a2.x + d2.x, a2.y + d2.y };
#pragma unroll
    for (int h = 0; h < 6; h++) {
        float u = (v[h] > 0.f) ? v[h] : 0.2f * v[h];
        atomicAdd(&g_s[d * 6 + h], __expf(u));
    }
}

__global__ void k_sinv() {
    int i = blockIdx.x * blockDim.x + threadIdx.x;
    if (i < NN * H) g_s[i] = (1.f / 6.f) / (g_s[i] + 1e-16f);
}

// ---------------- phase A: per-src head-reduced messages ---------------------
// warp per src: read xp row once, emit y_e[64] per outgoing edge (streamed).
__global__ void __launch_bounds__(256) k_phaseA() {
    int n = (blockIdx.x * blockDim.x + threadIdx.x) >> 5;
    int lane = threadIdx.x & 31;
    if (n >= NN) return;
    float asl = (lane < 6) ? g_as[n * 6 + lane] : 0.f;
    float2 r[6];
    const float* xpr = g_xp + (size_t)n * HD;
#pragma unroll
    for (int h = 0; h < 6; h++)
        r[h] = *(const float2*)(xpr + h * 64 + 2 * lane);
    int beg = g_srcptr[n], end = g_srcptr[n + 1];
    int p = beg;
    for (; p + 1 < end; p += 2) {
        int d0 = g_sdst[p], d1 = g_sdst[p + 1];
        float a0 = 0.f, a1 = 0.f;
        if (lane < 6) {
            float t0 = asl + g_ad[d0 * 6 + lane];
            float t1 = asl + g_ad[d1 * 6 + lane];
            t0 = (t0 > 0.f) ? t0 : 0.2f * t0;
            t1 = (t1 > 0.f) ? t1 : 0.2f * t1;
            a0 = __expf(t0) * g_s[d0 * 6 + lane];
            a1 = __expf(t1) * g_s[d1 * 6 + lane];
        }
        float2 y0 = make_float2(0.f, 0.f), y1 = y0;
#pragma unroll
        for (int h = 0; h < 6; h++) {
            float b0 = __shfl_sync(0xffffffffu, a0, h);
            float b1 = __shfl_sync(0xffffffffu, a1, h);
            y0.x += b0 * r[h].x; y0.y += b0 * r[h].y;
            y1.x += b1 * r[h].x; y1.y += b1 * r[h].y;
        }
        *(float2*)(g_y + (size_t)p * 64 + 2 * lane) = y0;
        *(float2*)(g_y + (size_t)(p + 1) * 64 + 2 * lane) = y1;
    }
    if (p < end) {
        int d0 = g_sdst[p];
        float a0 = 0.f;
        if (lane < 6) {
            float t0 = asl + g_ad[d0 * 6 + lane];
            t0 = (t0 > 0.f) ? t0 : 0.2f * t0;
            a0 = __expf(t0) * g_s[d0 * 6 + lane];
        }
        float2 y0 = make_float2(0.f, 0.f);
#pragma unroll
        for (int h = 0; h < 6; h++) {
            float b0 = __shfl_sync(0xffffffffu, a0, h);
            y0.x += b0 * r[h].x; y0.y += b0 * r[h].y;
        }
        *(float2*)(g_y + (size_t)p * 64 + 2 * lane) = y0;
    }
}

// ---------------- phase B: per-dst reduction of messages ---------------------
__global__ void __launch_bounds__(256) k_phaseB(const float* __restrict__ bias, int layer) {
    int n = (blockIdx.x * blockDim.x + threadIdx.x) >> 5;
    int lane = threadIdx.x & 31;
    if (n >= NN) return;
    float* __restrict__ xout = (layer == 0) ? g_x1 : g_x2;
    int beg = g_dstptr[n], end = g_dstptr[n + 1];
    float2 acc = make_float2(0.f, 0.f);
    int p = beg;
    for (; p + 3 < end; p += 4) {
        int e0 = g_edpos[p], e1 = g_edpos[p + 1];
        int e2 = g_edpos[p + 2], e3 = g_edpos[p + 3];
        float2 v0 = *(const float2*)(g_y + (size_t)e0 * 64 + 2 * lane);
        float2 v1 = *(const float2*)(g_y + (size_t)e1 * 64 + 2 * lane);
        float2 v2 = *(const float2*)(g_y + (size_t)e2 * 64 + 2 * lane);
        float2 v3 = *(const float2*)(g_y + (size_t)e3 * 64 + 2 * lane);
        acc.x += (v0.x + v1.x) + (v2.x + v3.x);
        acc.y += (v0.y + v1.y) + (v2.y + v3.y);
    }
    for (; p < end; p++) {
        int e0 = g_edpos[p];
        float2 v0 = *(const float2*)(g_y + (size_t)e0 * 64 + 2 * lane);
        acc.x += v0.x; acc.y += v0.y;
    }
    float2 bv = *(const float2*)(bias + 2 * lane);
    *(float2*)(xout + (size_t)n * 64 + 2 * lane) = make_float2(acc.x + bv.x, acc.y + bv.y);
}

// ---------------- transpose x2 [NN,64] -> x2t [64,NN] (into g_xp) ------------
__global__ void k_transpose() {
    __shared__ float tile[32][33];
    int nb = blockIdx.x * 32, db = blockIdx.y * 32;
    int tx = threadIdx.x, ty = threadIdx.y;
#pragma unroll
    for (int i = ty; i < 32; i += 8) {
        int n = nb + i;
        tile[i][tx] = (n < NN) ? g_x2[(size_t)n * D + db + tx] : 0.f;
    }
    __syncthreads();
#pragma unroll
    for (int i = ty; i < 32; i += 8) {
        int n = nb + tx;
        if (n < NN) g_xp[(size_t)(db + i) * NN + n] = tile[tx][i];
    }
}

__global__ void k_zero_pool() {
    int i = blockIdx.x * blockDim.x + threadIdx.x;
    if (i < BATCH * D) g_pool[i] = 0.f;
}

// ================= mma.sync tf32 pooling GEMM (3xTF32 compensated) ===========
#define PPK 50
#define PKSPAN (NN / PPK)      // 1000

__global__ void __launch_bounds__(256) k_pool_mma(const float* __restrict__ item) {
    int t = threadIdx.x;
    int wid = t >> 5, lane = t & 31;
    int m0 = blockIdx.x * 256 + wid * 32;
    int kbeg = blockIdx.y * PKSPAN;

    int r = lane >> 2, c = lane & 3;
    const float* pA0 = item + (size_t)(m0 + r) * NN;
    const float* pA1 = item + (size_t)(m0 + r + 8) * NN;
    const float* pA2 = item + (size_t)(m0 + r + 16) * NN;
    const float* pA3 = item + (size_t)(m0 + r + 24) * NN;
    const float* pB  = g_xp + (size_t)(lane >> 2) * NN + c;

    float acc[2][8][4];
#pragma unroll
    for (int mt = 0; mt < 2; mt++)
#pragma unroll
        for (int nt = 0; nt < 8; nt++)
#pragma unroll
            for (int i = 0; i < 4; i++) acc[mt][nt][i] = 0.f;

    for (int ch = 0; ch < PKSPAN / 8; ch++) {
        int kb = kbeg + ch * 8 + c;
        float a00 = pA0[kb], a01 = pA1[kb], a02 = pA0[kb + 4], a03 = pA1[kb + 4];
        float a10 = pA2[kb], a11 = pA3[kb], a12 = pA2[kb + 4], a13 = pA3[kb + 4];
        unsigned ah[2][4], al[2][4];
        ah[0][0] = f2tf(a00); al[0][0] = f2tf(a00 - __uint_as_float(ah[0][0]));
        ah[0][1] = f2tf(a01); al[0][1] = f2tf(a01 - __uint_as_float(ah[0][1]));
        ah[0][2] = f2tf(a02); al[0][2] = f2tf(a02 - __uint_as_float(ah[0][2]));
        ah[0][3] = f2tf(a03); al[0][3] = f2tf(a03 - __uint_as_float(ah[0][3]));
        ah[1][0] = f2tf(a10); al[1][0] = f2tf(a10 - __uint_as_float(ah[1][0]));
        ah[1][1] = f2tf(a11); al[1][1] = f2tf(a11 - __uint_as_float(ah[1][1]));
        ah[1][2] = f2tf(a12); al[1][2] = f2tf(a12 - __uint_as_float(ah[1][2]));
        ah[1][3] = f2tf(a13); al[1][3] = f2tf(a13 - __uint_as_float(ah[1][3]));

        int kbb = kbeg + ch * 8;
#pragma unroll
        for (int nt = 0; nt < 8; nt++) {
            const float* bp = pB + (size_t)nt * 8 * NN;
            float b0r = bp[kbb];
            float b1r = bp[kbb + 4];
            unsigned bh0 = f2tf(b0r), bh1 = f2tf(b1r);
            unsigned bl0 = f2tf(b0r - __uint_as_float(bh0));
            unsigned bl1 = f2tf(b1r - __uint_as_float(bh1));
#pragma unroll
            for (int mt = 0; mt < 2; mt++) {
                mma_tf32(acc[mt][nt], ah[mt][0], ah[mt][1], ah[mt][2], ah[mt][3], bh0, bh1);
                mma_tf32(acc[mt][nt], ah[mt][0], ah[mt][1], ah[mt][2], ah[mt][3], bl0, bl1);
                mma_tf32(acc[mt][nt], al[mt][0], al[mt][1], al[mt][2], al[mt][3], bh0, bh1);
            }
        }
    }

#pragma unroll
    for (int mt = 0; mt < 2; mt++) {
        int row = m0 + mt * 16 + r;
#pragma unroll
        for (int nt = 0; nt < 8; nt++) {
            int col = nt * 8 + 2 * c;
            atomicAdd(&g_pool[row * D + col],           acc[mt][nt][0]);
            atomicAdd(&g_pool[row * D + col + 1],       acc[mt][nt][1]);
            atomicAdd(&g_pool[(row + 8) * D + col],     acc[mt][nt][2]);
            atomicAdd(&g_pool[(row + 8) * D + col + 1], acc[mt][nt][3]);
        }
    }
}

// ---------------- MLP head + sigmoid -----------------------------------------
__global__ void __launch_bounds__(128) k_mlp(const int* __restrict__ user,
                                             const float* __restrict__ u_table,
                                             const float* __restrict__ W0,
                                             const float* __restrict__ b0,
                                             const float* __restrict__ W1,
                                             const float* __restrict__ b1,
                                             float* __restrict__ out) {
    __shared__ float vec[128];
    __shared__ float red[128];
    int b = blockIdx.x, t = threadIdx.x;
    if (t < 64) vec[t] = u_table[(size_t)user[b] * 64 + t];
    else        vec[t] = g_pool[b * 64 + (t - 64)];
    __syncthreads();
    float h = b0[t];
#pragma unroll 8
    for (int k = 0; k < 128; k++) h += vec[k] * W0[k * 128 + t];
    red[t] = h * W1[t];
    __syncthreads();
    for (int s = 64; s; s >>= 1) {
        if (t < s) red[t] += red[t + s];
        __syncthreads();
    }
    if (t == 0) {
        float z = red[0] + b1[0];
        out[b] = 1.f / (1.f + expf(-z));
    }
}

// ---------------- launch -----------------------------------------------------
extern "C" void kernel_launch(void* const* d_in, const int* in_sizes, int n_in,
                              void* d_out, int out_size) {
    const int*   user  = (const int*)d_in[0];
    const float* item  = (const float*)d_in[1];
    const int*   eidx  = (const int*)d_in[3];
    const float* u_tab = (const float*)d_in[4];
    const float* i_tab = (const float*)d_in[5];
    const float* W0    = (const float*)d_in[6];
    const float* as0   = (const float*)d_in[7];
    const float* ad0   = (const float*)d_in[8];
    const float* b0    = (const float*)d_in[9];
    const float* W1    = (const float*)d_in[10];
    const float* as1   = (const float*)d_in[11];
    const float* ad1   = (const float*)d_in[12];
    const float* b1    = (const float*)d_in[13];
    const float* lW0   = (const float*)d_in[14];
    const float* lb0   = (const float*)d_in[15];
    const float* lW1   = (const float*)d_in[16];
    const float* lb1   = (const float*)d_in[17];
    float* out = (float*)d_out;

    const int GXP = (NN + 31) / 32;

    // dual CSR build (src-major for phaseA, dst-major for phaseB)
    k_init2<<<(NN + 255) / 256, 256>>>();
    k_count2<<<(NE + 255) / 256, 256>>>(eidx);
    k_scan2<<<2, 1024>>>();
    k_scat_src<<<(ET + 255) / 256, 256>>>(eidx);
    k_scat_dst<<<(ET + 255) / 256, 256>>>(eidx);

    // GAT layer 0
    k_gemm_mma<<<GXP, 256>>>(i_tab, W0, 0);
    k_prew<<<1, 384>>>(W0, as0, ad0);
    k_attn2<<<(NN + 127) / 128, 128>>>(i_tab, 0);
    k_zero_s<<<(NN * H + 255) / 256, 256>>>();
    k_pass1<<<(ET + 255) / 256, 256>>>(eidx);
    k_sinv<<<(NN * H + 255) / 256, 256>>>();
    k_phaseA<<<6250, 256>>>();
    k_phaseB<<<6250, 256>>>(b0, 0);

    // GAT layer 1
    k_gemm_mma<<<GXP, 256>>>(i_tab, W1, 1);
    k_prew<<<1, 384>>>(W1, as1, ad1);
    k_attn2<<<(NN + 127) / 128, 128>>>(i_tab, 1);
    k_zero_s<<<(NN * H + 255) / 256, 256>>>();
    k_pass1<<<(ET + 255) / 256, 256>>>(eidx);
    k_sinv<<<(NN * H + 255) / 256, 256>>>();
    k_phaseA<<<6250, 256>>>();
    k_phaseB<<<6250, 256>>>(b1, 1);

    // pooling GEMM + MLP head
    k_transpose<<<dim3((NN + 31) / 32, 2), dim3(32, 8)>>>();
    k_zero_pool<<<(BATCH * D + 255) / 256, 256>>>();
    k_pool_mma<<<dim3(BATCH / 256, PPK), 256>>>(item);
    k_mlp<<<BATCH, 128>>>(user, u_tab, lW0, lb0, lW1, lb1, out);
}

// round 11
// speedup vs baseline: 1.2456x; 1.2456x over previous
#include <cuda_runtime.h>
#include <cuda_bf16.h>

#define NN 50000
#define NE 800000
#define ET (NE + NN)        // 850000 edges incl. self loops
#define D 64
#define H 6
#define HD 384
#define BATCH 1024

// ---------------- scratch (device globals; no allocations allowed) ----------
__device__ float g_xp[(size_t)NN * HD];           // reused as x2^T for pooling only
__device__ __nv_bfloat16 g_xpb[(size_t)NN * HD];  // bf16 xp for edge gather (38.4MB, L2-resident)
__device__ float g_as[NN * H];
__device__ float g_ad[NN * H];
__device__ float g_x1[NN * D];
__device__ float g_x2[NN * D];
__device__ int   g_rowptr[NN + 1];
__device__ int   g_cursor[NN];
__device__ int   g_esrc[ET];
__device__ float g_pool[BATCH * D];
__device__ float g_wad[64 * 12];            // folded attention weights

// ---------------- mma.sync tf32 helpers (frag layout verified in R6) ---------
__device__ __forceinline__ unsigned f2tf(float x) {
    unsigned r; asm("cvt.rna.tf32.f32 %0, %1;" : "=r"(r) : "f"(x)); return r;
}
__device__ __forceinline__ void mma_tf32(float* c, unsigned a0, unsigned a1,
                                         unsigned a2, unsigned a3,
                                         unsigned b0, unsigned b1) {
    asm volatile(
        "mma.sync.aligned.m16n8k8.row.col.f32.tf32.tf32.f32 "
        "{%0,%1,%2,%3}, {%4,%5,%6,%7}, {%8,%9}, {%0,%1,%2,%3};"
        : "+f"(c[0]), "+f"(c[1]), "+f"(c[2]), "+f"(c[3])
        : "r"(a0), "r"(a1), "r"(a2), "r"(a3), "r"(b0), "r"(b1));
}

// ---------------- CSR build (dst-major) --------------------------------------
__global__ void k_init_deg() {
    int i = blockIdx.x * blockDim.x + threadIdx.x;
    if (i < NN) g_cursor[i] = 1;                 // self loop
}

__global__ void k_count(const int* __restrict__ ei) {
    int e = blockIdx.x * blockDim.x + threadIdx.x;
    if (e < NE) atomicAdd(&g_cursor[ei[NE + e]], 1);
}

__global__ void __launch_bounds__(1024) k_scan() {
    __shared__ int wsum[32];
    int tid = threadIdx.x;
    int lane = tid & 31, warp = tid >> 5;
    int base = tid * 49;
    int s = 0;
    for (int i = 0; i < 49; i++) {
        int idx = base + i;
        if (idx < NN) s += g_cursor[idx];
    }
    int x = s;
#pragma unroll
    for (int off = 1; off < 32; off <<= 1) {
        int y = __shfl_up_sync(0xffffffffu, x, off);
        if (lane >= off) x += y;
    }
    if (lane == 31) wsum[warp] = x;
    __syncthreads();
    if (warp == 0) {
        int w = wsum[lane];
#pragma unroll
        for (int off = 1; off < 32; off <<= 1) {
            int y = __shfl_up_sync(0xffffffffu, w, off);
            if (lane >= off) w += y;
        }
        wsum[lane] = w;
    }
    __syncthreads();
    int tbase = x - s + (warp ? wsum[warp - 1] : 0);
    int run = tbase;
    for (int i = 0; i < 49; i++) {
        int idx = base + i;
        if (idx < NN) {
            int v = g_cursor[idx];
            g_rowptr[idx] = run;
            g_cursor[idx] = run;
            run += v;
        }
    }
    if (tid == 1023) g_rowptr[NN] = tbase + s;
}

__global__ void k_scatter(const int* __restrict__ ei) {
    int i = blockIdx.x * blockDim.x + threadIdx.x;
    if (i < NE) {
        int s = ei[i], d = ei[NE + i];
        int pos = atomicAdd(&g_cursor[d], 1);
        g_esrc[pos] = s;
    } else if (i < ET) {
        int n = i - NE;
        int pos = atomicAdd(&g_cursor[n], 1);
        g_esrc[pos] = n;
    }
}

// ---------------- xp = x @ W via mma.sync (3xTF32), bf16 output --------------
__global__ void __launch_bounds__(256) k_gemm_mma(const float* __restrict__ x0,
                                                  const float* __restrict__ W, int layer) {
    const float* __restrict__ x = (layer == 0) ? x0 : g_x1;
    int t = threadIdx.x;
    int wid = t >> 5, lane = t & 31;
    int r = lane >> 2, c = lane & 3;
    int mg = wid >> 2;
    int noff = (wid & 3) * 96;
    int m0 = blockIdx.x * 32 + mg * 16;
    int rowA = m0 + r;
    bool vA = rowA < NN, vB = (rowA + 8) < NN;

    float acc[12][4];
#pragma unroll
    for (int nt = 0; nt < 12; nt++)
#pragma unroll
        for (int i = 0; i < 4; i++) acc[nt][i] = 0.f;

    const float* pA0 = x + (size_t)rowA * 64;
    const float* pA1 = x + (size_t)(rowA + 8) * 64;
    int nlane = noff + r;

#pragma unroll
    for (int k8 = 0; k8 < 8; k8++) {
        int kc = k8 * 8 + c;
        float a00 = vA ? pA0[kc]     : 0.f;
        float a01 = vB ? pA1[kc]     : 0.f;
        float a02 = vA ? pA0[kc + 4] : 0.f;
        float a03 = vB ? pA1[kc + 4] : 0.f;
        unsigned ah0 = f2tf(a00), ah1 = f2tf(a01), ah2 = f2tf(a02), ah3 = f2tf(a03);
        unsigned al0 = f2tf(a00 - __uint_as_float(ah0));
        unsigned al1 = f2tf(a01 - __uint_as_float(ah1));
        unsigned al2 = f2tf(a02 - __uint_as_float(ah2));
        unsigned al3 = f2tf(a03 - __uint_as_float(ah3));

        const float* w0p = W + (size_t)kc * HD + nlane;
        const float* w1p = W + (size_t)(kc + 4) * HD + nlane;
#pragma unroll
        for (int nt = 0; nt < 12; nt++) {
            float b0r = w0p[nt * 8];
            float b1r = w1p[nt * 8];
            unsigned bh0 = f2tf(b0r), bh1 = f2tf(b1r);
            unsigned bl0 = f2tf(b0r - __uint_as_float(bh0));
            unsigned bl1 = f2tf(b1r - __uint_as_float(bh1));
            mma_tf32(acc[nt], ah0, ah1, ah2, ah3, bh0, bh1);
            mma_tf32(acc[nt], ah0, ah1, ah2, ah3, bl0, bl1);
            mma_tf32(acc[nt], al0, al1, al2, al3, bh0, bh1);
        }
    }
    // epilogue: c0->(r,2c) c1->(r,2c+1) c2->(r+8,2c) c3->(r+8,2c+1), bf16x2 stores
#pragma unroll
    for (int nt = 0; nt < 12; nt++) {
        int n0 = noff + nt * 8 + 2 * c;
        if (vA) *(__nv_bfloat162*)&g_xpb[(size_t)rowA * HD + n0] =
                    __floats2bfloat162_rn(acc[nt][0], acc[nt][1]);
        if (vB) *(__nv_bfloat162*)&g_xpb[(size_t)(rowA + 8) * HD + n0] =
                    __floats2bfloat162_rn(acc[nt][2], acc[nt][3]);
    }
}

// ---------------- folded attention weights -----------------------------------
__global__ void __launch_bounds__(384) k_prew(const float* __restrict__ W,
                                              const float* __restrict__ asrc,
                                              const float* __restrict__ adst) {
    int t = threadIdx.x;
    int k = t % 64, h = t / 64;
    float sa = 0.f, sd = 0.f;
    const float* wr = W + (size_t)k * HD + h * 64;
#pragma unroll 8
    for (int d = 0; d < 64; d++) {
        float wv = wr[d];
        sa += wv * asrc[h * 64 + d];
        sd += wv * adst[h * 64 + d];
    }
    g_wad[k * 12 + h]     = sa;
    g_wad[k * 12 + 6 + h] = sd;
}

// ---------------- as/ad = x @ wad (full fp32) --------------------------------
__global__ void __launch_bounds__(128) k_attn2(const float* __restrict__ x0, int layer) {
    __shared__ float sw[64 * 12];
    const float* __restrict__ x = (layer == 0) ? x0 : g_x1;
    int t = threadIdx.x;
#pragma unroll
    for (int i = t; i < 768; i += 128) sw[i] = g_wad[i];
    __syncthreads();
    int n = blockIdx.x * 128 + t;
    if (n >= NN) return;
    float as[6], ad[6];
#pragma unroll
    for (int h = 0; h < 6; h++) { as[h] = 0.f; ad[h] = 0.f; }
    const float4* xr = (const float4*)(x + (size_t)n * 64);
#pragma unroll
    for (int k4 = 0; k4 < 16; k4++) {
        float4 xv = xr[k4];
        const float* w0 = &sw[(4 * k4) * 12];
#pragma unroll
        for (int h = 0; h < 6; h++) {
            as[h] += xv.x * w0[h]      + xv.y * w0[12 + h]
                   + xv.z * w0[24 + h] + xv.w * w0[36 + h];
            ad[h] += xv.x * w0[6 + h]      + xv.y * w0[18 + h]
                   + xv.z * w0[30 + h] + xv.w * w0[42 + h];
        }
    }
#pragma unroll
    for (int h = 0; h < 6; h++) {
        g_as[n * 6 + h] = as[h];
        g_ad[n * 6 + h] = ad[h];
    }
}

// ---------------- fused softmax-sum + weighted gather (bf16 operand) ---------
__global__ void __launch_bounds__(256) k_edge(const float* __restrict__ bias, int layer) {
    int warp = (blockIdx.x * blockDim.x + threadIdx.x) >> 5;
    int lane = threadIdx.x & 31;
    if (warp >= NN) return;
    float* __restrict__ xout = (layer == 0) ? g_x1 : g_x2;
    int n = warp;
    int beg = g_rowptr[n], end = g_rowptr[n + 1];

    float adh[6];
    {
        const float2* adp = (const float2*)(g_ad + n * 6);
        float2 a0 = adp[0], a1 = adp[1], a2 = adp[2];
        adh[0] = a0.x; adh[1] = a0.y; adh[2] = a1.x;
        adh[3] = a1.y; adh[4] = a2.x; adh[5] = a2.y;
    }

    // pass 1: per-head sum of exp(leaky(v)) over incoming edges
    float sm[6];
#pragma unroll
    for (int t = 0; t < 6; t++) sm[t] = 0.f;
    for (int e = beg + lane; e < end; e += 32) {
        int src = g_esrc[e];
        const float2* asp = (const float2*)(g_as + src * 6);
        float2 s0 = asp[0], s1 = asp[1], s2 = asp[2];
        float v[6] = { s0.x + adh[0], s0.y + adh[1], s1.x + adh[2],
                       s1.y + adh[3], s2.x + adh[4], s2.y + adh[5] };
#pragma unroll
        for (int t = 0; t < 6; t++) {
            float u = (v[t] > 0.f) ? v[t] : 0.2f * v[t];
            sm[t] += __expf(u);
        }
    }
#pragma unroll
    for (int t = 0; t < 6; t++)
#pragma unroll
        for (int off = 16; off; off >>= 1)
            sm[t] += __shfl_xor_sync(0xffffffffu, sm[t], off);

    float adh_l = adh[0], inv_l = sm[0];
#pragma unroll
    for (int t = 1; t < 6; t++) {
        if (lane == t) { adh_l = adh[t]; inv_l = sm[t]; }
    }
    inv_l = 1.f / (inv_l + 1e-16f);

    // pass 2: accumulate alpha * xpb[src]; 3 x LDG.64 per edge, 2-edge pipeline
    float4 a0 = make_float4(0.f, 0.f, 0.f, 0.f);
    float4 a1 = a0, a2 = a0;
    int half = lane >> 4;               // head = 2j + half
    int coff = 4 * (lane & 15);

    int e = beg;
    for (; e + 1 < end; e += 2) {
        int s0 = g_esrc[e], s1 = g_esrc[e + 1];
        float al0 = 0.f, al1 = 0.f;
        if (lane < 6) {
            float v0 = g_as[s0 * 6 + lane] + adh_l;
            float v1 = g_as[s1 * 6 + lane] + adh_l;
            v0 = (v0 > 0.f) ? v0 : 0.2f * v0;
            v1 = (v1 > 0.f) ? v1 : 0.2f * v1;
            al0 = __expf(v0) * inv_l;
            al1 = __expf(v1) * inv_l;
        }
        const uint2* r0 = (const uint2*)(g_xpb + (size_t)s0 * HD);
        const uint2* r1 = (const uint2*)(g_xpb + (size_t)s1 * HD);
        uint2 v00 = r0[lane], v01 = r0[32 + lane], v02 = r0[64 + lane];
        uint2 v10 = r1[lane], v11 = r1[32 + lane], v12 = r1[64 + lane];
#pragma unroll
        for (int j = 0; j < 3; j++) {
            float b0 = __shfl_sync(0xffffffffu, al0, 2 * j + half);
            float b1 = __shfl_sync(0xffffffffu, al1, 2 * j + half);
            float4* acc = (j == 0) ? &a0 : (j == 1) ? &a1 : &a2;
            uint2 w0 = (j == 0) ? v00 : (j == 1) ? v01 : v02;
            uint2 w1 = (j == 0) ? v10 : (j == 1) ? v11 : v12;
            float2 lo0 = __bfloat1622float2(*(const __nv_bfloat162*)&w0.x);
            float2 hi0 = __bfloat1622float2(*(const __nv_bfloat162*)&w0.y);
            float2 lo1 = __bfloat1622float2(*(const __nv_bfloat162*)&w1.x);
            float2 hi1 = __bfloat1622float2(*(const __nv_bfloat162*)&w1.y);
            acc->x += b0 * lo0.x + b1 * lo1.x;
            acc->y += b0 * lo0.y + b1 * lo1.y;
            acc->z += b0 * hi0.x + b1 * hi1.x;
            acc->w += b0 * hi0.y + b1 * hi1.y;
        }
    }
    if (e < end) {
        int s0 = g_esrc[e];
        float al0 = 0.f;
        if (lane < 6) {
            float v0 = g_as[s0 * 6 + lane] + adh_l;
            v0 = (v0 > 0.f) ? v0 : 0.2f * v0;
            al0 = __expf(v0) * inv_l;
        }
        const uint2* r0 = (const uint2*)(g_xpb + (size_t)s0 * HD);
        uint2 v00 = r0[lane], v01 = r0[32 + lane], v02 = r0[64 + lane];
#pragma unroll
        for (int j = 0; j < 3; j++) {
            float b0 = __shfl_sync(0xffffffffu, al0, 2 * j + half);
            float4* acc = (j == 0) ? &a0 : (j == 1) ? &a1 : &a2;
            uint2 w0 = (j == 0) ? v00 : (j == 1) ? v01 : v02;
            float2 lo0 = __bfloat1622float2(*(const __nv_bfloat162*)&w0.x);
            float2 hi0 = __bfloat1622float2(*(const __nv_bfloat162*)&w0.y);
            acc->x += b0 * lo0.x;
            acc->y += b0 * lo0.y;
            acc->z += b0 * hi0.x;
            acc->w += b0 * hi0.y;
        }
    }
    // combine 3 heads held by this lane, then the other 3 from lane^16
    float4 s;
    s.x = a0.x + a1.x + a2.x;
    s.y = a0.y + a1.y + a2.y;
    s.z = a0.z + a1.z + a2.z;
    s.w = a0.w + a1.w + a2.w;
    s.x += __shfl_xor_sync(0xffffffffu, s.x, 16);
    s.y += __shfl_xor_sync(0xffffffffu, s.y, 16);
    s.z += __shfl_xor_sync(0xffffffffu, s.z, 16);
    s.w += __shfl_xor_sync(0xffffffffu, s.w, 16);
    if (lane < 16) {
        float4 bv = *(const float4*)(bias + coff);
        float4 o;
        o.x = s.x * (1.f / 6.f) + bv.x;
        o.y = s.y * (1.f / 6.f) + bv.y;
        o.z = s.z * (1.f / 6.f) + bv.z;
        o.w = s.w * (1.f / 6.f) + bv.w;
        *(float4*)(xout + (size_t)n * 64 + coff) = o;
    }
}

// ---------------- transpose x2 [NN,64] -> x2t [64,NN] (into g_xp) ------------
__global__ void k_transpose() {
    __shared__ float tile[32][33];
    int nb = blockIdx.x * 32, db = blockIdx.y * 32;
    int tx = threadIdx.x, ty = threadIdx.y;
#pragma unroll
    for (int i = ty; i < 32; i += 8) {
        int n = nb + i;
        tile[i][tx] = (n < NN) ? g_x2[(size_t)n * D + db + tx] : 0.f;
    }
    __syncthreads();
#pragma unroll
    for (int i = ty; i < 32; i += 8) {
        int n = nb + tx;
        if (n < NN) g_xp[(size_t)(db + i) * NN + n] = tile[tx][i];
    }
}

__global__ void k_zero_pool() {
    int i = blockIdx.x * blockDim.x + threadIdx.x;
    if (i < BATCH * D) g_pool[i] = 0.f;
}

// ================= mma.sync tf32 pooling GEMM (3xTF32 compensated) ===========
#define PPK 50
#define PKSPAN (NN / PPK)      // 1000

__global__ void __launch_bounds__(256) k_pool_mma(const float* __restrict__ item) {
    int t = threadIdx.x;
    int wid = t >> 5, lane = t & 31;
    int m0 = blockIdx.x * 256 + wid * 32;
    int kbeg = blockIdx.y * PKSPAN;

    int r = lane >> 2, c = lane & 3;
    const float* pA0 = item + (size_t)(m0 + r) * NN;
    const float* pA1 = item + (size_t)(m0 + r + 8) * NN;
    const float* pA2 = item + (size_t)(m0 + r + 16) * NN;
    const float* pA3 = item + (size_t)(m0 + r + 24) * NN;
    const float* pB  = g_xp + (size_t)(lane >> 2) * NN + c;

    float acc[2][8][4];
#pragma unroll
    for (int mt = 0; mt < 2; mt++)
#pragma unroll
        for (int nt = 0; nt < 8; nt++)
#pragma unroll
            for (int i = 0; i < 4; i++) acc[mt][nt][i] = 0.f;

    for (int ch = 0; ch < PKSPAN / 8; ch++) {
        int kb = kbeg + ch * 8 + c;
        float a00 = pA0[kb], a01 = pA1[kb], a02 = pA0[kb + 4], a03 = pA1[kb + 4];
        float a10 = pA2[kb], a11 = pA3[kb], a12 = pA2[kb + 4], a13 = pA3[kb + 4];
        unsigned ah[2][4], al[2][4];
        ah[0][0] = f2tf(a00); al[0][0] = f2tf(a00 - __uint_as_float(ah[0][0]));
        ah[0][1] = f2tf(a01); al[0][1] = f2tf(a01 - __uint_as_float(ah[0][1]));
        ah[0][2] = f2tf(a02); al[0][2] = f2tf(a02 - __uint_as_float(ah[0][2]));
        ah[0][3] = f2tf(a03); al[0][3] = f2tf(a03 - __uint_as_float(ah[0][3]));
        ah[1][0] = f2tf(a10); al[1][0] = f2tf(a10 - __uint_as_float(ah[1][0]));
        ah[1][1] = f2tf(a11); al[1][1] = f2tf(a11 - __uint_as_float(ah[1][1]));
        ah[1][2] = f2tf(a12); al[1][2] = f2tf(a12 - __uint_as_float(ah[1][2]));
        ah[1][3] = f2tf(a13); al[1][3] = f2tf(a13 - __uint_as_float(ah[1][3]));

        int kbb = kbeg + ch * 8;
#pragma unroll
        for (int nt = 0; nt < 8; nt++) {
            const float* bp = pB + (size_t)nt * 8 * NN;
            float b0r = bp[kbb];
            float b1r = bp[kbb + 4];
            unsigned bh0 = f2tf(b0r), bh1 = f2tf(b1r);
            unsigned bl0 = f2tf(b0r - __uint_as_float(bh0));
            unsigned bl1 = f2tf(b1r - __uint_as_float(bh1));
#pragma unroll
            for (int mt = 0; mt < 2; mt++) {
                mma_tf32(acc[mt][nt], ah[mt][0], ah[mt][1], ah[mt][2], ah[mt][3], bh0, bh1);
                mma_tf32(acc[mt][nt], ah[mt][0], ah[mt][1], ah[mt][2], ah[mt][3], bl0, bl1);
                mma_tf32(acc[mt][nt], al[mt][0], al[mt][1], al[mt][2], al[mt][3], bh0, bh1);
            }
        }
    }

#pragma unroll
    for (int mt = 0; mt < 2; mt++) {
        int row = m0 + mt * 16 + r;
#pragma unroll
        for (int nt = 0; nt < 8; nt++) {
            int col = nt * 8 + 2 * c;
            atomicAdd(&g_pool[row * D + col],           acc[mt][nt][0]);
            atomicAdd(&g_pool[row * D + col + 1],       acc[mt][nt][1]);
            atomicAdd(&g_pool[(row + 8) * D + col],     acc[mt][nt][2]);
            atomicAdd(&g_pool[(row + 8) * D + col + 1], acc[mt][nt][3]);
        }
    }
}

// ---------------- MLP head + sigmoid -----------------------------------------
__global__ void __launch_bounds__(128) k_mlp(const int* __restrict__ user,
                                             const float* __restrict__ u_table,
                                             const float* __restrict__ W0,
                                             const float* __restrict__ b0,
                                             const float* __restrict__ W1,
                                             const float* __restrict__ b1,
                                             float* __restrict__ out) {
    __shared__ float vec[128];
    __shared__ float red[128];
    int b = blockIdx.x, t = threadIdx.x;
    if (t < 64) vec[t] = u_table[(size_t)user[b] * 64 + t];
    else        vec[t] = g_pool[b * 64 + (t - 64)];
    __syncthreads();
    float h = b0[t];
#pragma unroll 8
    for (int k = 0; k < 128; k++) h += vec[k] * W0[k * 128 + t];
    red[t] = h * W1[t];
    __syncthreads();
    for (int s = 64; s; s >>= 1) {
        if (t < s) red[t] += red[t + s];
        __syncthreads();
    }
    if (t == 0) {
        float z = red[0] + b1[0];
        out[b] = 1.f / (1.f + expf(-z));
    }
}

// ---------------- launch -----------------------------------------------------
extern "C" void kernel_launch(void* const* d_in, const int* in_sizes, int n_in,
                              void* d_out, int out_size) {
    const int*   user  = (const int*)d_in[0];
    const float* item  = (const float*)d_in[1];
    const int*   eidx  = (const int*)d_in[3];
    const float* u_tab = (const float*)d_in[4];
    const float* i_tab = (const float*)d_in[5];
    const float* W0    = (const float*)d_in[6];
    const float* as0   = (const float*)d_in[7];
    const float* ad0   = (const float*)d_in[8];
    const float* b0    = (const float*)d_in[9];
    const float* W1    = (const float*)d_in[10];
    const float* as1   = (const float*)d_in[11];
    const float* ad1   = (const float*)d_in[12];
    const float* b1    = (const float*)d_in[13];
    const float* lW0   = (const float*)d_in[14];
    const float* lb0   = (const float*)d_in[15];
    const float* lW1   = (const float*)d_in[16];
    const float* lb1   = (const float*)d_in[17];
    float* out = (float*)d_out;

    const int GXP = (NN + 31) / 32;

    // CSR by destination
    k_init_deg<<<(NN + 255) / 256, 256>>>();
    k_count<<<(NE + 255) / 256, 256>>>(eidx);
    k_scan<<<1, 1024>>>();
    k_scatter<<<(ET + 255) / 256, 256>>>(eidx);

    // GAT layer 0
    k_gemm_mma<<<GXP, 256>>>(i_tab, W0, 0);
    k_prew<<<1, 384>>>(W0, as0, ad0);
    k_attn2<<<(NN + 127) / 128, 128>>>(i_tab, 0);
    k_edge<<<6250, 256>>>(b0, 0);

    // GAT layer 1
    k_gemm_mma<<<GXP, 256>>>(i_tab, W1, 1);
    k_prew<<<1, 384>>>(W1, as1, ad1);
    k_attn2<<<(NN + 127) / 128, 128>>>(i_tab, 1);
    k_edge<<<6250, 256>>>(b1, 1);

    // pooling GEMM + MLP head
    k_transpose<<<dim3((NN + 31) / 32, 2), dim3(32, 8)>>>();
    k_zero_pool<<<(BATCH * D + 255) / 256, 256>>>();
    k_pool_mma<<<dim3(BATCH / 256, PPK), 256>>>(item);
    k_mlp<<<BATCH, 128>>>(user, u_tab, lW0, lb0, lW1, lb1, out);
}

// round 12
// speedup vs baseline: 1.3318x; 1.0693x over previous
#include <cuda_runtime.h>
#include <cuda_bf16.h>

#define NN 50000
#define NE 800000
#define ET (NE + NN)        // 850000 edges incl. self loops
#define D 64
#define H 6
#define HD 384
#define BATCH 1024

// ---------------- scratch (device globals; no allocations allowed) ----------
__device__ float g_xp[(size_t)NN * HD];           // reused as x2^T for pooling only
__device__ __nv_bfloat16 g_xpb[(size_t)NN * HD];  // bf16 xp for edge gather (38.4MB, L2-resident)
__device__ float g_as[NN * H];
__device__ float g_ad[NN * H];
__device__ float g_x1[NN * D];
__device__ float g_x2[NN * D];
__device__ int   g_rowptr[NN + 1];
__device__ int   g_cursor[NN];
__device__ int   g_esrc[ET];
__device__ float g_pool[BATCH * D];
__device__ float g_wad[64 * 12];            // folded attention weights

// ---------------- mma.sync tf32 helpers (frag layout verified in R6) ---------
__device__ __forceinline__ unsigned f2tf(float x) {
    unsigned r; asm("cvt.rna.tf32.f32 %0, %1;" : "=r"(r) : "f"(x)); return r;
}
__device__ __forceinline__ void mma_tf32(float* c, unsigned a0, unsigned a1,
                                         unsigned a2, unsigned a3,
                                         unsigned b0, unsigned b1) {
    asm volatile(
        "mma.sync.aligned.m16n8k8.row.col.f32.tf32.tf32.f32 "
        "{%0,%1,%2,%3}, {%4,%5,%6,%7}, {%8,%9}, {%0,%1,%2,%3};"
        : "+f"(c[0]), "+f"(c[1]), "+f"(c[2]), "+f"(c[3])
        : "r"(a0), "r"(a1), "r"(a2), "r"(a3), "r"(b0), "r"(b1));
}

// ---------------- CSR build (dst-major) --------------------------------------
__global__ void k_init_deg() {
    int i = blockIdx.x * blockDim.x + threadIdx.x;
    if (i < NN) g_cursor[i] = 1;                 // self loop
}

__global__ void k_count(const int* __restrict__ ei) {
    int e = blockIdx.x * blockDim.x + threadIdx.x;
    if (e < NE) atomicAdd(&g_cursor[ei[NE + e]], 1);
}

// single-block scan staged through smem: coalesced gmem, conflict-free smem
// (stride 49 = 17 mod 32 -> all lanes hit distinct banks)
__global__ void __launch_bounds__(1024) k_scan() {
    extern __shared__ int sd[];                  // NN ints (200KB dynamic)
    __shared__ int wsum[32];
    int tid = threadIdx.x;
    int lane = tid & 31, warp = tid >> 5;

    for (int i = tid; i < NN; i += 1024) sd[i] = g_cursor[i];
    __syncthreads();

    int base = tid * 49;
    int s = 0;
    for (int i = 0; i < 49; i++) {
        int idx = base + i;
        if (idx < NN) s += sd[idx];
    }
    int x = s;
#pragma unroll
    for (int off = 1; off < 32; off <<= 1) {
        int y = __shfl_up_sync(0xffffffffu, x, off);
        if (lane >= off) x += y;
    }
    if (lane == 31) wsum[warp] = x;
    __syncthreads();
    if (warp == 0) {
        int w = wsum[lane];
#pragma unroll
        for (int off = 1; off < 32; off <<= 1) {
            int y = __shfl_up_sync(0xffffffffu, w, off);
            if (lane >= off) w += y;
        }
        wsum[lane] = w;
    }
    __syncthreads();
    int tbase = x - s + (warp ? wsum[warp - 1] : 0);
    int run = tbase;
    for (int i = 0; i < 49; i++) {
        int idx = base + i;
        if (idx < NN) {
            int v = sd[idx];
            sd[idx] = run;
            run += v;
        }
    }
    __syncthreads();
    for (int i = tid; i < NN; i += 1024) {
        int v = sd[i];
        g_rowptr[i] = v;
        g_cursor[i] = v;
    }
    if (tid == 1023) g_rowptr[NN] = tbase + s;   // == ET
}

__global__ void k_scatter(const int* __restrict__ ei) {
    int i = blockIdx.x * blockDim.x + threadIdx.x;
    if (i < NE) {
        int s = ei[i], d = ei[NE + i];
        int pos = atomicAdd(&g_cursor[d], 1);
        g_esrc[pos] = s;
    } else if (i < ET) {
        int n = i - NE;
        int pos = atomicAdd(&g_cursor[n], 1);
        g_esrc[pos] = n;
    }
}

// ---------------- xp = x @ W via mma.sync (3xTF32), bf16 output --------------
__global__ void __launch_bounds__(256) k_gemm_mma(const float* __restrict__ x0,
                                                  const float* __restrict__ W, int layer) {
    const float* __restrict__ x = (layer == 0) ? x0 : g_x1;
    int t = threadIdx.x;
    int wid = t >> 5, lane = t & 31;
    int r = lane >> 2, c = lane & 3;
    int mg = wid >> 2;
    int noff = (wid & 3) * 96;
    int m0 = blockIdx.x * 32 + mg * 16;
    int rowA = m0 + r;
    bool vA = rowA < NN, vB = (rowA + 8) < NN;

    float acc[12][4];
#pragma unroll
    for (int nt = 0; nt < 12; nt++)
#pragma unroll
        for (int i = 0; i < 4; i++) acc[nt][i] = 0.f;

    const float* pA0 = x + (size_t)rowA * 64;
    const float* pA1 = x + (size_t)(rowA + 8) * 64;
    int nlane = noff + r;

#pragma unroll
    for (int k8 = 0; k8 < 8; k8++) {
        int kc = k8 * 8 + c;
        float a00 = vA ? pA0[kc]     : 0.f;
        float a01 = vB ? pA1[kc]     : 0.f;
        float a02 = vA ? pA0[kc + 4] : 0.f;
        float a03 = vB ? pA1[kc + 4] : 0.f;
        unsigned ah0 = f2tf(a00), ah1 = f2tf(a01), ah2 = f2tf(a02), ah3 = f2tf(a03);
        unsigned al0 = f2tf(a00 - __uint_as_float(ah0));
        unsigned al1 = f2tf(a01 - __uint_as_float(ah1));
        unsigned al2 = f2tf(a02 - __uint_as_float(ah2));
        unsigned al3 = f2tf(a03 - __uint_as_float(ah3));

        const float* w0p = W + (size_t)kc * HD + nlane;
        const float* w1p = W + (size_t)(kc + 4) * HD + nlane;
#pragma unroll
        for (int nt = 0; nt < 12; nt++) {
            float b0r = w0p[nt * 8];
            float b1r = w1p[nt * 8];
            unsigned bh0 = f2tf(b0r), bh1 = f2tf(b1r);
            unsigned bl0 = f2tf(b0r - __uint_as_float(bh0));
            unsigned bl1 = f2tf(b1r - __uint_as_float(bh1));
            mma_tf32(acc[nt], ah0, ah1, ah2, ah3, bh0, bh1);
            mma_tf32(acc[nt], ah0, ah1, ah2, ah3, bl0, bl1);
            mma_tf32(acc[nt], al0, al1, al2, al3, bh0, bh1);
        }
    }
#pragma unroll
    for (int nt = 0; nt < 12; nt++) {
        int n0 = noff + nt * 8 + 2 * c;
        if (vA) *(__nv_bfloat162*)&g_xpb[(size_t)rowA * HD + n0] =
                    __floats2bfloat162_rn(acc[nt][0], acc[nt][1]);
        if (vB) *(__nv_bfloat162*)&g_xpb[(size_t)(rowA + 8) * HD + n0] =
                    __floats2bfloat162_rn(acc[nt][2], acc[nt][3]);
    }
}

// ---------------- folded attention weights -----------------------------------
__global__ void __launch_bounds__(384) k_prew(const float* __restrict__ W,
                                              const float* __restrict__ asrc,
                                              const float* __restrict__ adst) {
    int t = threadIdx.x;
    int k = t % 64, h = t / 64;
    float sa = 0.f, sd = 0.f;
    const float* wr = W + (size_t)k * HD + h * 64;
#pragma unroll 8
    for (int d = 0; d < 64; d++) {
        float wv = wr[d];
        sa += wv * asrc[h * 64 + d];
        sd += wv * adst[h * 64 + d];
    }
    g_wad[k * 12 + h]     = sa;
    g_wad[k * 12 + 6 + h] = sd;
}

// ---------------- as/ad = x @ wad (full fp32) --------------------------------
__global__ void __launch_bounds__(128) k_attn2(const float* __restrict__ x0, int layer) {
    __shared__ float sw[64 * 12];
    const float* __restrict__ x = (layer == 0) ? x0 : g_x1;
    int t = threadIdx.x;
#pragma unroll
    for (int i = t; i < 768; i += 128) sw[i] = g_wad[i];
    __syncthreads();
    int n = blockIdx.x * 128 + t;
    if (n >= NN) return;
    float as[6], ad[6];
#pragma unroll
    for (int h = 0; h < 6; h++) { as[h] = 0.f; ad[h] = 0.f; }
    const float4* xr = (const float4*)(x + (size_t)n * 64);
#pragma unroll
    for (int k4 = 0; k4 < 16; k4++) {
        float4 xv = xr[k4];
        const float* w0 = &sw[(4 * k4) * 12];
#pragma unroll
        for (int h = 0; h < 6; h++) {
            as[h] += xv.x * w0[h]      + xv.y * w0[12 + h]
                   + xv.z * w0[24 + h] + xv.w * w0[36 + h];
            ad[h] += xv.x * w0[6 + h]      + xv.y * w0[18 + h]
                   + xv.z * w0[30 + h] + xv.w * w0[42 + h];
        }
    }
#pragma unroll
    for (int h = 0; h < 6; h++) {
        g_as[n * 6 + h] = as[h];
        g_ad[n * 6 + h] = ad[h];
    }
}

// ---------------- single-pass softmax + gather (bf16 operand) ----------------
// Accumulate unnormalized p*x AND per-head p-sums in ONE edge loop; scale at end.
__global__ void __launch_bounds__(256) k_edge(const float* __restrict__ bias, int layer) {
    int warp = (blockIdx.x * blockDim.x + threadIdx.x) >> 5;
    int lane = threadIdx.x & 31;
    if (warp >= NN) return;
    float* __restrict__ xout = (layer == 0) ? g_x1 : g_x2;
    int n = warp;
    int beg = g_rowptr[n], end = g_rowptr[n + 1];

    float adh_l = (lane < 6) ? g_ad[n * 6 + lane] : 0.f;
    float smsum = 0.f;                   // per-head p-sum, lives on lanes 0..5

    float4 a0 = make_float4(0.f, 0.f, 0.f, 0.f);
    float4 a1 = a0, a2 = a0;
    int half = lane >> 4;                // head = 2j + half for chunk j
    int coff = 4 * (lane & 15);

    int e = beg;
    for (; e + 1 < end; e += 2) {
        int s0 = g_esrc[e], s1 = g_esrc[e + 1];
        float p0 = 0.f, p1 = 0.f;
        if (lane < 6) {
            float v0 = g_as[s0 * 6 + lane] + adh_l;
            float v1 = g_as[s1 * 6 + lane] + adh_l;
            v0 = (v0 > 0.f) ? v0 : 0.2f * v0;
            v1 = (v1 > 0.f) ? v1 : 0.2f * v1;
            p0 = __expf(v0);
            p1 = __expf(v1);
            smsum += p0 + p1;
        }
        const uint2* r0 = (const uint2*)(g_xpb + (size_t)s0 * HD);
        const uint2* r1 = (const uint2*)(g_xpb + (size_t)s1 * HD);
        uint2 v00 = r0[lane], v01 = r0[32 + lane], v02 = r0[64 + lane];
        uint2 v10 = r1[lane], v11 = r1[32 + lane], v12 = r1[64 + lane];
#pragma unroll
        for (int j = 0; j < 3; j++) {
            float b0 = __shfl_sync(0xffffffffu, p0, 2 * j + half);
            float b1 = __shfl_sync(0xffffffffu, p1, 2 * j + half);
            float4* acc = (j == 0) ? &a0 : (j == 1) ? &a1 : &a2;
            uint2 w0 = (j == 0) ? v00 : (j == 1) ? v01 : v02;
            uint2 w1 = (j == 0) ? v10 : (j == 1) ? v11 : v12;
            float2 lo0 = __bfloat1622float2(*(const __nv_bfloat162*)&w0.x);
            float2 hi0 = __bfloat1622float2(*(const __nv_bfloat162*)&w0.y);
            float2 lo1 = __bfloat1622float2(*(const __nv_bfloat162*)&w1.x);
            float2 hi1 = __bfloat1622float2(*(const __nv_bfloat162*)&w1.y);
            acc->x += b0 * lo0.x + b1 * lo1.x;
            acc->y += b0 * lo0.y + b1 * lo1.y;
            acc->z += b0 * hi0.x + b1 * hi1.x;
            acc->w += b0 * hi0.y + b1 * hi1.y;
        }
    }
    if (e < end) {
        int s0 = g_esrc[e];
        float p0 = 0.f;
        if (lane < 6) {
            float v0 = g_as[s0 * 6 + lane] + adh_l;
            v0 = (v0 > 0.f) ? v0 : 0.2f * v0;
            p0 = __expf(v0);
            smsum += p0;
        }
        const uint2* r0 = (const uint2*)(g_xpb + (size_t)s0 * HD);
        uint2 v00 = r0[lane], v01 = r0[32 + lane], v02 = r0[64 + lane];
#pragma unroll
        for (int j = 0; j < 3; j++) {
            float b0 = __shfl_sync(0xffffffffu, p0, 2 * j + half);
            float4* acc = (j == 0) ? &a0 : (j == 1) ? &a1 : &a2;
            uint2 w0 = (j == 0) ? v00 : (j == 1) ? v01 : v02;
            float2 lo0 = __bfloat1622float2(*(const __nv_bfloat162*)&w0.x);
            float2 hi0 = __bfloat1622float2(*(const __nv_bfloat162*)&w0.y);
            acc->x += b0 * lo0.x;
            acc->y += b0 * lo0.y;
            acc->z += b0 * hi0.x;
            acc->w += b0 * hi0.y;
        }
    }
    // per-head scale (1/6)/(s_h + eps), broadcast to the lanes that need it
    float scale = (1.f / 6.f) / (smsum + 1e-16f);   // valid on lanes 0..5
    float f0 = __shfl_sync(0xffffffffu, scale, 0 + half);   // head 2*0+half
    float f1 = __shfl_sync(0xffffffffu, scale, 2 + half);   // head 2*1+half
    float f2 = __shfl_sync(0xffffffffu, scale, 4 + half);   // head 2*2+half
    float4 s;
    s.x = a0.x * f0 + a1.x * f1 + a2.x * f2;
    s.y = a0.y * f0 + a1.y * f1 + a2.y * f2;
    s.z = a0.z * f0 + a1.z * f1 + a2.z * f2;
    s.w = a0.w * f0 + a1.w * f1 + a2.w * f2;
    s.x += __shfl_xor_sync(0xffffffffu, s.x, 16);
    s.y += __shfl_xor_sync(0xffffffffu, s.y, 16);
    s.z += __shfl_xor_sync(0xffffffffu, s.z, 16);
    s.w += __shfl_xor_sync(0xffffffffu, s.w, 16);
    if (lane < 16) {
        float4 bv = *(const float4*)(bias + coff);
        float4 o;
        o.x = s.x + bv.x;
        o.y = s.y + bv.y;
        o.z = s.z + bv.z;
        o.w = s.w + bv.w;
        *(float4*)(xout + (size_t)n * 64 + coff) = o;
    }
}

// ---------------- transpose x2 [NN,64] -> x2t [64,NN] (into g_xp) ------------
__global__ void k_transpose() {
    __shared__ float tile[32][33];
    int nb = blockIdx.x * 32, db = blockIdx.y * 32;
    int tx = threadIdx.x, ty = threadIdx.y;
#pragma unroll
    for (int i = ty; i < 32; i += 8) {
        int n = nb + i;
        tile[i][tx] = (n < NN) ? g_x2[(size_t)n * D + db + tx] : 0.f;
    }
    __syncthreads();
#pragma unroll
    for (int i = ty; i < 32; i += 8) {
        int n = nb + tx;
        if (n < NN) g_xp[(size_t)(db + i) * NN + n] = tile[tx][i];
    }
}

__global__ void k_zero_pool() {
    int i = blockIdx.x * blockDim.x + threadIdx.x;
    if (i < BATCH * D) g_pool[i] = 0.f;
}

// ================= mma.sync tf32 pooling GEMM (3xTF32 compensated) ===========
#define PPK 50
#define PKSPAN (NN / PPK)      // 1000

__global__ void __launch_bounds__(256) k_pool_mma(const float* __restrict__ item) {
    int t = threadIdx.x;
    int wid = t >> 5, lane = t & 31;
    int m0 = blockIdx.x * 256 + wid * 32;
    int kbeg = blockIdx.y * PKSPAN;

    int r = lane >> 2, c = lane & 3;
    const float* pA0 = item + (size_t)(m0 + r) * NN;
    const float* pA1 = item + (size_t)(m0 + r + 8) * NN;
    const float* pA2 = item + (size_t)(m0 + r + 16) * NN;
    const float* pA3 = item + (size_t)(m0 + r + 24) * NN;
    const float* pB  = g_xp + (size_t)(lane >> 2) * NN + c;

    float acc[2][8][4];
#pragma unroll
    for (int mt = 0; mt < 2; mt++)
#pragma unroll
        for (int nt = 0; nt < 8; nt++)
#pragma unroll
            for (int i = 0; i < 4; i++) acc[mt][nt][i] = 0.f;

    for (int ch = 0; ch < PKSPAN / 8; ch++) {
        int kb = kbeg + ch * 8 + c;
        float a00 = pA0[kb], a01 = pA1[kb], a02 = pA0[kb + 4], a03 = pA1[kb + 4];
        float a10 = pA2[kb], a11 = pA3[kb], a12 = pA2[kb + 4], a13 = pA3[kb + 4];
        unsigned ah[2][4], al[2][4];
        ah[0][0] = f2tf(a00); al[0][0] = f2tf(a00 - __uint_as_float(ah[0][0]));
        ah[0][1] = f2tf(a01); al[0][1] = f2tf(a01 - __uint_as_float(ah[0][1]));
        ah[0][2] = f2tf(a02); al[0][2] = f2tf(a02 - __uint_as_float(ah[0][2]));
        ah[0][3] = f2tf(a03); al[0][3] = f2tf(a03 - __uint_as_float(ah[0][3]));
        ah[1][0] = f2tf(a10); al[1][0] = f2tf(a10 - __uint_as_float(ah[1][0]));
        ah[1][1] = f2tf(a11); al[1][1] = f2tf(a11 - __uint_as_float(ah[1][1]));
        ah[1][2] = f2tf(a12); al[1][2] = f2tf(a12 - __uint_as_float(ah[1][2]));
        ah[1][3] = f2tf(a13); al[1][3] = f2tf(a13 - __uint_as_float(ah[1][3]));

        int kbb = kbeg + ch * 8;
#pragma unroll
        for (int nt = 0; nt < 8; nt++) {
            const float* bp = pB + (size_t)nt * 8 * NN;
            float b0r = bp[kbb];
            float b1r = bp[kbb + 4];
            unsigned bh0 = f2tf(b0r), bh1 = f2tf(b1r);
            unsigned bl0 = f2tf(b0r - __uint_as_float(bh0));
            unsigned bl1 = f2tf(b1r - __uint_as_float(bh1));
#pragma unroll
            for (int mt = 0; mt < 2; mt++) {
                mma_tf32(acc[mt][nt], ah[mt][0], ah[mt][1], ah[mt][2], ah[mt][3], bh0, bh1);
                mma_tf32(acc[mt][nt], ah[mt][0], ah[mt][1], ah[mt][2], ah[mt][3], bl0, bl1);
                mma_tf32(acc[mt][nt], al[mt][0], al[mt][1], al[mt][2], al[mt][3], bh0, bh1);
            }
        }
    }

#pragma unroll
    for (int mt = 0; mt < 2; mt++) {
        int row = m0 + mt * 16 + r;
#pragma unroll
        for (int nt = 0; nt < 8; nt++) {
            int col = nt * 8 + 2 * c;
            atomicAdd(&g_pool[row * D + col],           acc[mt][nt][0]);
            atomicAdd(&g_pool[row * D + col + 1],       acc[mt][nt][1]);
            atomicAdd(&g_pool[(row + 8) * D + col],     acc[mt][nt][2]);
            atomicAdd(&g_pool[(row + 8) * D + col + 1], acc[mt][nt][3]);
        }
    }
}

// ---------------- MLP head + sigmoid -----------------------------------------
__global__ void __launch_bounds__(128) k_mlp(const int* __restrict__ user,
                                             const float* __restrict__ u_table,
                                             const float* __restrict__ W0,
                                             const float* __restrict__ b0,
                                             const float* __restrict__ W1,
                                             const float* __restrict__ b1,
                                             float* __restrict__ out) {
    __shared__ float vec[128];
    __shared__ float red[128];
    int b = blockIdx.x, t = threadIdx.x;
    if (t < 64) vec[t] = u_table[(size_t)user[b] * 64 + t];
    else        vec[t] = g_pool[b * 64 + (t - 64)];
    __syncthreads();
    float h = b0[t];
#pragma unroll 8
    for (int k = 0; k < 128; k++) h += vec[k] * W0[k * 128 + t];
    red[t] = h * W1[t];
    __syncthreads();
    for (int s = 64; s; s >>= 1) {
        if (t < s) red[t] += red[t + s];
        __syncthreads();
    }
    if (t == 0) {
        float z = red[0] + b1[0];
        out[b] = 1.f / (1.f + expf(-z));
    }
}

// ---------------- launch -----------------------------------------------------
extern "C" void kernel_launch(void* const* d_in, const int* in_sizes, int n_in,
                              void* d_out, int out_size) {
    const int*   user  = (const int*)d_in[0];
    const float* item  = (const float*)d_in[1];
    const int*   eidx  = (const int*)d_in[3];
    const float* u_tab = (const float*)d_in[4];
    const float* i_tab = (const float*)d_in[5];
    const float* W0    = (const float*)d_in[6];
    const float* as0   = (const float*)d_in[7];
    const float* ad0   = (const float*)d_in[8];
    const float* b0    = (const float*)d_in[9];
    const float* W1    = (const float*)d_in[10];
    const float* as1   = (const float*)d_in[11];
    const float* ad1   = (const float*)d_in[12];
    const float* b1    = (const float*)d_in[13];
    const float* lW0   = (const float*)d_in[14];
    const float* lb0   = (const float*)d_in[15];
    const float* lW1   = (const float*)d_in[16];
    const float* lb1   = (const float*)d_in[17];
    float* out = (float*)d_out;

    const int GXP = (NN + 31) / 32;
    const int SCAN_SMEM = NN * (int)sizeof(int);   // 200000 B dynamic smem

    static int scan_attr_set = 0;
    if (!scan_attr_set) {
        cudaFuncSetAttribute(k_scan, cudaFuncAttributeMaxDynamicSharedMemorySize, SCAN_SMEM);
        scan_attr_set = 1;
    }

    // CSR by destination
    k_init_deg<<<(NN + 255) / 256, 256>>>();
    k_count<<<(NE + 255) / 256, 256>>>(eidx);
    k_scan<<<1, 1024, SCAN_SMEM>>>();
    k_scatter<<<(ET + 255) / 256, 256>>>(eidx);

    // GAT layer 0
    k_gemm_mma<<<GXP, 256>>>(i_tab, W0, 0);
    k_prew<<<1, 384>>>(W0, as0, ad0);
    k_attn2<<<(NN + 127) / 128, 128>>>(i_tab, 0);
    k_edge<<<6250, 256>>>(b0, 0);

    // GAT layer 1
    k_gemm_mma<<<GXP, 256>>>(i_tab, W1, 1);
    k_prew<<<1, 384>>>(W1, as1, ad1);
    k_attn2<<<(NN + 127) / 128, 128>>>(i_tab, 1);
    k_edge<<<6250, 256>>>(b1, 1);

    // pooling GEMM + MLP head
    k_transpose<<<dim3((NN + 31) / 32, 2), dim3(32, 8)>>>();
    k_zero_pool<<<(BATCH * D + 255) / 256, 256>>>();
    k_pool_mma<<<dim3(BATCH / 256, PPK), 256>>>(item);
    k_mlp<<<BATCH, 128>>>(user, u_tab, lW0, lb0, lW1, lb1, out);
}

// round 13
// speedup vs baseline: 1.3802x; 1.0363x over previous
#include <cuda_runtime.h>
#include <cuda_bf16.h>

#define NN 50000
#define NE 800000
#define ET (NE + NN)        // 850000 edges incl. self loops
#define D 64
#define H 6
#define HD 384
#define BATCH 1024

// ---------------- scratch (device globals; no allocations allowed) ----------
__device__ float g_xp[(size_t)NN * HD];           // reused as x2^T for pooling only
__device__ __nv_bfloat16 g_xpb[(size_t)NN * HD];  // bf16 xp for edge gather (38.4MB, L2-resident)
__device__ float g_as[NN * H];
__device__ float g_ad[NN * H];
__device__ float g_x1[NN * D];
__device__ float g_x2[NN * D];
__device__ int   g_rowptr[NN + 1];
__device__ int   g_cursor[NN];
__device__ int   g_esrc[ET];
__device__ float g_pool[BATCH * D];
__device__ float g_wad[64 * 12];            // folded attention weights

// ---------------- mma.sync tf32 helpers (frag layout verified in R6) ---------
__device__ __forceinline__ unsigned f2tf(float x) {
    unsigned r; asm("cvt.rna.tf32.f32 %0, %1;" : "=r"(r) : "f"(x)); return r;
}
__device__ __forceinline__ void mma_tf32(float* c, unsigned a0, unsigned a1,
                                         unsigned a2, unsigned a3,
                                         unsigned b0, unsigned b1) {
    asm volatile(
        "mma.sync.aligned.m16n8k8.row.col.f32.tf32.tf32.f32 "
        "{%0,%1,%2,%3}, {%4,%5,%6,%7}, {%8,%9}, {%0,%1,%2,%3};"
        : "+f"(c[0]), "+f"(c[1]), "+f"(c[2]), "+f"(c[3])
        : "r"(a0), "r"(a1), "r"(a2), "r"(a3), "r"(b0), "r"(b1));
}

// exact bf16x2 -> 2x f32 via bit ops (no cvt)
__device__ __forceinline__ float bflo(unsigned w) { return __uint_as_float(w << 16); }
__device__ __forceinline__ float bfhi(unsigned w) { return __uint_as_float(w & 0xffff0000u); }

// ---------------- CSR build (dst-major) --------------------------------------
__global__ void k_init_deg() {
    int i = blockIdx.x * blockDim.x + threadIdx.x;
    if (i < NN) g_cursor[i] = 1;                 // self loop
}

__global__ void k_count(const int* __restrict__ ei) {
    int e = blockIdx.x * blockDim.x + threadIdx.x;
    if (e < NE) atomicAdd(&g_cursor[ei[NE + e]], 1);
}

// single-block scan staged through smem (coalesced gmem; stride 49 conflict-free)
__global__ void __launch_bounds__(1024) k_scan() {
    extern __shared__ int sd[];                  // NN ints (200KB dynamic)
    __shared__ int wsum[32];
    int tid = threadIdx.x;
    int lane = tid & 31, warp = tid >> 5;

    for (int i = tid; i < NN; i += 1024) sd[i] = g_cursor[i];
    __syncthreads();

    int base = tid * 49;
    int s = 0;
    for (int i = 0; i < 49; i++) {
        int idx = base + i;
        if (idx < NN) s += sd[idx];
    }
    int x = s;
#pragma unroll
    for (int off = 1; off < 32; off <<= 1) {
        int y = __shfl_up_sync(0xffffffffu, x, off);
        if (lane >= off) x += y;
    }
    if (lane == 31) wsum[warp] = x;
    __syncthreads();
    if (warp == 0) {
        int w = wsum[lane];
#pragma unroll
        for (int off = 1; off < 32; off <<= 1) {
            int y = __shfl_up_sync(0xffffffffu, w, off);
            if (lane >= off) w += y;
        }
        wsum[lane] = w;
    }
    __syncthreads();
    int tbase = x - s + (warp ? wsum[warp - 1] : 0);
    int run = tbase;
    for (int i = 0; i < 49; i++) {
        int idx = base + i;
        if (idx < NN) {
            int v = sd[idx];
            sd[idx] = run;
            run += v;
        }
    }
    __syncthreads();
    for (int i = tid; i < NN; i += 1024) {
        int v = sd[i];
        g_rowptr[i] = v;
        g_cursor[i] = v;
    }
    if (tid == 1023) g_rowptr[NN] = tbase + s;   // == ET
}

__global__ void k_scatter(const int* __restrict__ ei) {
    int i = blockIdx.x * blockDim.x + threadIdx.x;
    if (i < NE) {
        int s = ei[i], d = ei[NE + i];
        int pos = atomicAdd(&g_cursor[d], 1);
        g_esrc[pos] = s;
    } else if (i < ET) {
        int n = i - NE;
        int pos = atomicAdd(&g_cursor[n], 1);
        g_esrc[pos] = n;
    }
}

// ---------------- xp = x @ W via mma.sync (3xTF32), bf16 output --------------
__global__ void __launch_bounds__(256) k_gemm_mma(const float* __restrict__ x0,
                                                  const float* __restrict__ W, int layer) {
    const float* __restrict__ x = (layer == 0) ? x0 : g_x1;
    int t = threadIdx.x;
    int wid = t >> 5, lane = t & 31;
    int r = lane >> 2, c = lane & 3;
    int mg = wid >> 2;
    int noff = (wid & 3) * 96;
    int m0 = blockIdx.x * 32 + mg * 16;
    int rowA = m0 + r;
    bool vA = rowA < NN, vB = (rowA + 8) < NN;

    float acc[12][4];
#pragma unroll
    for (int nt = 0; nt < 12; nt++)
#pragma unroll
        for (int i = 0; i < 4; i++) acc[nt][i] = 0.f;

    const float* pA0 = x + (size_t)rowA * 64;
    const float* pA1 = x + (size_t)(rowA + 8) * 64;
    int nlane = noff + r;

#pragma unroll
    for (int k8 = 0; k8 < 8; k8++) {
        int kc = k8 * 8 + c;
        float a00 = vA ? pA0[kc]     : 0.f;
        float a01 = vB ? pA1[kc]     : 0.f;
        float a02 = vA ? pA0[kc + 4] : 0.f;
        float a03 = vB ? pA1[kc + 4] : 0.f;
        unsigned ah0 = f2tf(a00), ah1 = f2tf(a01), ah2 = f2tf(a02), ah3 = f2tf(a03);
        unsigned al0 = f2tf(a00 - __uint_as_float(ah0));
        unsigned al1 = f2tf(a01 - __uint_as_float(ah1));
        unsigned al2 = f2tf(a02 - __uint_as_float(ah2));
        unsigned al3 = f2tf(a03 - __uint_as_float(ah3));

        const float* w0p = W + (size_t)kc * HD + nlane;
        const float* w1p = W + (size_t)(kc + 4) * HD + nlane;
#pragma unroll
        for (int nt = 0; nt < 12; nt++) {
            float b0r = w0p[nt * 8];
            float b1r = w1p[nt * 8];
            unsigned bh0 = f2tf(b0r), bh1 = f2tf(b1r);
            unsigned bl0 = f2tf(b0r - __uint_as_float(bh0));
            unsigned bl1 = f2tf(b1r - __uint_as_float(bh1));
            mma_tf32(acc[nt], ah0, ah1, ah2, ah3, bh0, bh1);
            mma_tf32(acc[nt], ah0, ah1, ah2, ah3, bl0, bl1);
            mma_tf32(acc[nt], al0, al1, al2, al3, bh0, bh1);
        }
    }
#pragma unroll
    for (int nt = 0; nt < 12; nt++) {
        int n0 = noff + nt * 8 + 2 * c;
        if (vA) *(__nv_bfloat162*)&g_xpb[(size_t)rowA * HD + n0] =
                    __floats2bfloat162_rn(acc[nt][0], acc[nt][1]);
        if (vB) *(__nv_bfloat162*)&g_xpb[(size_t)(rowA + 8) * HD + n0] =
                    __floats2bfloat162_rn(acc[nt][2], acc[nt][3]);
    }
}

// ---------------- folded attention weights -----------------------------------
__global__ void __launch_bounds__(384) k_prew(const float* __restrict__ W,
                                              const float* __restrict__ asrc,
                                              const float* __restrict__ adst) {
    int t = threadIdx.x;
    int k = t % 64, h = t / 64;
    float sa = 0.f, sd = 0.f;
    const float* wr = W + (size_t)k * HD + h * 64;
#pragma unroll 8
    for (int d = 0; d < 64; d++) {
        float wv = wr[d];
        sa += wv * asrc[h * 64 + d];
        sd += wv * adst[h * 64 + d];
    }
    g_wad[k * 12 + h]     = sa;
    g_wad[k * 12 + 6 + h] = sd;
}

// ---------------- as/ad = x @ wad (full fp32) --------------------------------
__global__ void __launch_bounds__(128) k_attn2(const float* __restrict__ x0, int layer) {
    __shared__ float sw[64 * 12];
    const float* __restrict__ x = (layer == 0) ? x0 : g_x1;
    int t = threadIdx.x;
#pragma unroll
    for (int i = t; i < 768; i += 128) sw[i] = g_wad[i];
    __syncthreads();
    int n = blockIdx.x * 128 + t;
    if (n >= NN) return;
    float as[6], ad[6];
#pragma unroll
    for (int h = 0; h < 6; h++) { as[h] = 0.f; ad[h] = 0.f; }
    const float4* xr = (const float4*)(x + (size_t)n * 64);
#pragma unroll
    for (int k4 = 0; k4 < 16; k4++) {
        float4 xv = xr[k4];
        const float* w0 = &sw[(4 * k4) * 12];
#pragma unroll
        for (int h = 0; h < 6; h++) {
            as[h] += xv.x * w0[h]      + xv.y * w0[12 + h]
                   + xv.z * w0[24 + h] + xv.w * w0[36 + h];
            ad[h] += xv.x * w0[6 + h]      + xv.y * w0[18 + h]
                   + xv.z * w0[30 + h] + xv.w * w0[42 + h];
        }
    }
#pragma unroll
    for (int h = 0; h < 6; h++) {
        g_as[n * 6 + h] = as[h];
        g_ad[n * 6 + h] = ad[h];
    }
}

// ---------------- single-pass softmax + gather (bf16, 4-edge pipeline) -------
__global__ void __launch_bounds__(256) k_edge(const float* __restrict__ bias, int layer) {
    int warp = (blockIdx.x * blockDim.x + threadIdx.x) >> 5;
    int lane = threadIdx.x & 31;
    if (warp >= NN) return;
    float* __restrict__ xout = (layer == 0) ? g_x1 : g_x2;
    int n = warp;
    int beg = g_rowptr[n], end = g_rowptr[n + 1];

    float adh_l = (lane < 6) ? g_ad[n * 6 + lane] : 0.f;
    float smsum = 0.f;                   // per-head p-sum, lanes 0..5

    float4 a0 = make_float4(0.f, 0.f, 0.f, 0.f);
    float4 a1 = a0, a2 = a0;
    int half = lane >> 4;                // head = 2j + half for chunk j
    int coff = 4 * (lane & 15);

    int e = beg;
    // 4-edge pipeline: 12 independent LDG.64 in flight
    for (; e + 3 < end; e += 4) {
        int s0 = g_esrc[e],     s1 = g_esrc[e + 1];
        int s2 = g_esrc[e + 2], s3 = g_esrc[e + 3];
        float p0 = 0.f, p1 = 0.f, p2 = 0.f, p3 = 0.f;
        if (lane < 6) {
            float v0 = g_as[s0 * 6 + lane] + adh_l;
            float v1 = g_as[s1 * 6 + lane] + adh_l;
            float v2 = g_as[s2 * 6 + lane] + adh_l;
            float v3 = g_as[s3 * 6 + lane] + adh_l;
            v0 = (v0 > 0.f) ? v0 : 0.2f * v0;
            v1 = (v1 > 0.f) ? v1 : 0.2f * v1;
            v2 = (v2 > 0.f) ? v2 : 0.2f * v2;
            v3 = (v3 > 0.f) ? v3 : 0.2f * v3;
            p0 = __expf(v0); p1 = __expf(v1);
            p2 = __expf(v2); p3 = __expf(v3);
            smsum += (p0 + p1) + (p2 + p3);
        }
        const uint2* r0 = (const uint2*)(g_xpb + (size_t)s0 * HD);
        const uint2* r1 = (const uint2*)(g_xpb + (size_t)s1 * HD);
        const uint2* r2 = (const uint2*)(g_xpb + (size_t)s2 * HD);
        const uint2* r3 = (const uint2*)(g_xpb + (size_t)s3 * HD);
        uint2 v0c[3], v1c[3], v2c[3], v3c[3];
#pragma unroll
        for (int j = 0; j < 3; j++) {
            v0c[j] = r0[32 * j + lane];
            v1c[j] = r1[32 * j + lane];
            v2c[j] = r2[32 * j + lane];
            v3c[j] = r3[32 * j + lane];
        }
#pragma unroll
        for (int j = 0; j < 3; j++) {
            float b0 = __shfl_sync(0xffffffffu, p0, 2 * j + half);
            float b1 = __shfl_sync(0xffffffffu, p1, 2 * j + half);
            float b2 = __shfl_sync(0xffffffffu, p2, 2 * j + half);
            float b3 = __shfl_sync(0xffffffffu, p3, 2 * j + half);
            float4* acc = (j == 0) ? &a0 : (j == 1) ? &a1 : &a2;
            acc->x += b0 * bflo(v0c[j].x) + b1 * bflo(v1c[j].x)
                    + b2 * bflo(v2c[j].x) + b3 * bflo(v3c[j].x);
            acc->y += b0 * bfhi(v0c[j].x) + b1 * bfhi(v1c[j].x)
                    + b2 * bfhi(v2c[j].x) + b3 * bfhi(v3c[j].x);
            acc->z += b0 * bflo(v0c[j].y) + b1 * bflo(v1c[j].y)
                    + b2 * bflo(v2c[j].y) + b3 * bflo(v3c[j].y);
            acc->w += b0 * bfhi(v0c[j].y) + b1 * bfhi(v1c[j].y)
                    + b2 * bfhi(v2c[j].y) + b3 * bfhi(v3c[j].y);
        }
    }
    // remainder (0..3 edges)
    for (; e < end; e++) {
        int s0 = g_esrc[e];
        float p0 = 0.f;
        if (lane < 6) {
            float v0 = g_as[s0 * 6 + lane] + adh_l;
            v0 = (v0 > 0.f) ? v0 : 0.2f * v0;
            p0 = __expf(v0);
            smsum += p0;
        }
        const uint2* r0 = (const uint2*)(g_xpb + (size_t)s0 * HD);
        uint2 vc[3];
#pragma unroll
        for (int j = 0; j < 3; j++) vc[j] = r0[32 * j + lane];
#pragma unroll
        for (int j = 0; j < 3; j++) {
            float b0 = __shfl_sync(0xffffffffu, p0, 2 * j + half);
            float4* acc = (j == 0) ? &a0 : (j == 1) ? &a1 : &a2;
            acc->x += b0 * bflo(vc[j].x);
            acc->y += b0 * bfhi(vc[j].x);
            acc->z += b0 * bflo(vc[j].y);
            acc->w += b0 * bfhi(vc[j].y);
        }
    }
    // per-head scale (1/6)/(s_h + eps)
    float scale = (1.f / 6.f) / (smsum + 1e-16f);   // valid on lanes 0..5
    float f0 = __shfl_sync(0xffffffffu, scale, 0 + half);
    float f1 = __shfl_sync(0xffffffffu, scale, 2 + half);
    float f2 = __shfl_sync(0xffffffffu, scale, 4 + half);
    float4 s;
    s.x = a0.x * f0 + a1.x * f1 + a2.x * f2;
    s.y = a0.y * f0 + a1.y * f1 + a2.y * f2;
    s.z = a0.z * f0 + a1.z * f1 + a2.z * f2;
    s.w = a0.w * f0 + a1.w * f1 + a2.w * f2;
    s.x += __shfl_xor_sync(0xffffffffu, s.x, 16);
    s.y += __shfl_xor_sync(0xffffffffu, s.y, 16);
    s.z += __shfl_xor_sync(0xffffffffu, s.z, 16);
    s.w += __shfl_xor_sync(0xffffffffu, s.w, 16);
    if (lane < 16) {
        float4 bv = *(const float4*)(bias + coff);
        float4 o;
        o.x = s.x + bv.x;
        o.y = s.y + bv.y;
        o.z = s.z + bv.z;
        o.w = s.w + bv.w;
        *(float4*)(xout + (size_t)n * 64 + coff) = o;
    }
}

// ---------------- transpose x2 [NN,64] -> x2t [64,NN] (into g_xp) ------------
__global__ void k_transpose() {
    __shared__ float tile[32][33];
    int nb = blockIdx.x * 32, db = blockIdx.y * 32;
    int tx = threadIdx.x, ty = threadIdx.y;
#pragma unroll
    for (int i = ty; i < 32; i += 8) {
        int n = nb + i;
        tile[i][tx] = (n < NN) ? g_x2[(size_t)n * D + db + tx] : 0.f;
    }
    __syncthreads();
#pragma unroll
    for (int i = ty; i < 32; i += 8) {
        int n = nb + tx;
        if (n < NN) g_xp[(size_t)(db + i) * NN + n] = tile[tx][i];
    }
}

__global__ void k_zero_pool() {
    int i = blockIdx.x * blockDim.x + threadIdx.x;
    if (i < BATCH * D) g_pool[i] = 0.f;
}

// ================= mma.sync tf32 pooling GEMM (3xTF32 compensated) ===========
#define PPK 50
#define PKSPAN (NN / PPK)      // 1000

__global__ void __launch_bounds__(256) k_pool_mma(const float* __restrict__ item) {
    int t = threadIdx.x;
    int wid = t >> 5, lane = t & 31;
    int m0 = blockIdx.x * 256 + wid * 32;
    int kbeg = blockIdx.y * PKSPAN;

    int r = lane >> 2, c = lane & 3;
    const float* pA0 = item + (size_t)(m0 + r) * NN;
    const float* pA1 = item + (size_t)(m0 + r + 8) * NN;
    const float* pA2 = item + (size_t)(m0 + r + 16) * NN;
    const float* pA3 = item + (size_t)(m0 + r + 24) * NN;
    const float* pB  = g_xp + (size_t)(lane >> 2) * NN + c;

    float acc[2][8][4];
#pragma unroll
    for (int mt = 0; mt < 2; mt++)
#pragma unroll
        for (int nt = 0; nt < 8; nt++)
#pragma unroll
            for (int i = 0; i < 4; i++) acc[mt][nt][i] = 0.f;

    for (int ch = 0; ch < PKSPAN / 8; ch++) {
        int kb = kbeg + ch * 8 + c;
        float a00 = pA0[kb], a01 = pA1[kb], a02 = pA0[kb + 4], a03 = pA1[kb + 4];
        float a10 = pA2[kb], a11 = pA3[kb], a12 = pA2[kb + 4], a13 = pA3[kb + 4];
        unsigned ah[2][4], al[2][4];
        ah[0][0] = f2tf(a00); al[0][0] = f2tf(a00 - __uint_as_float(ah[0][0]));
        ah[0][1] = f2tf(a01); al[0][1] = f2tf(a01 - __uint_as_float(ah[0][1]));
        ah[0][2] = f2tf(a02); al[0][2] = f2tf(a02 - __uint_as_float(ah[0][2]));
        ah[0][3] = f2tf(a03); al[0][3] = f2tf(a03 - __uint_as_float(ah[0][3]));
        ah[1][0] = f2tf(a10); al[1][0] = f2tf(a10 - __uint_as_float(ah[1][0]));
        ah[1][1] = f2tf(a11); al[1][1] = f2tf(a11 - __uint_as_float(ah[1][1]));
        ah[1][2] = f2tf(a12); al[1][2] = f2tf(a12 - __uint_as_float(ah[1][2]));
        ah[1][3] = f2tf(a13); al[1][3] = f2tf(a13 - __uint_as_float(ah[1][3]));

        int kbb = kbeg + ch * 8;
#pragma unroll
        for (int nt = 0; nt < 8; nt++) {
            const float* bp = pB + (size_t)nt * 8 * NN;
            float b0r = bp[kbb];
            float b1r = bp[kbb + 4];
            unsigned bh0 = f2tf(b0r), bh1 = f2tf(b1r);
            unsigned bl0 = f2tf(b0r - __uint_as_float(bh0));
            unsigned bl1 = f2tf(b1r - __uint_as_float(bh1));
#pragma unroll
            for (int mt = 0; mt < 2; mt++) {
                mma_tf32(acc[mt][nt], ah[mt][0], ah[mt][1], ah[mt][2], ah[mt][3], bh0, bh1);
                mma_tf32(acc[mt][nt], ah[mt][0], ah[mt][1], ah[mt][2], ah[mt][3], bl0, bl1);
                mma_tf32(acc[mt][nt], al[mt][0], al[mt][1], al[mt][2], al[mt][3], bh0, bh1);
            }
        }
    }

#pragma unroll
    for (int mt = 0; mt < 2; mt++) {
        int row = m0 + mt * 16 + r;
#pragma unroll
        for (int nt = 0; nt < 8; nt++) {
            int col = nt * 8 + 2 * c;
            atomicAdd(&g_pool[row * D + col],           acc[mt][nt][0]);
            atomicAdd(&g_pool[row * D + col + 1],       acc[mt][nt][1]);
            atomicAdd(&g_pool[(row + 8) * D + col],     acc[mt][nt][2]);
            atomicAdd(&g_pool[(row + 8) * D + col + 1], acc[mt][nt][3]);
        }
    }
}

// ---------------- MLP head + sigmoid -----------------------------------------
__global__ void __launch_bounds__(128) k_mlp(const int* __restrict__ user,
                                             const float* __restrict__ u_table,
                                             const float* __restrict__ W0,
                                             const float* __restrict__ b0,
                                             const float* __restrict__ W1,
                                             const float* __restrict__ b1,
                                             float* __restrict__ out) {
    __shared__ float vec[128];
    __shared__ float red[128];
    int b = blockIdx.x, t = threadIdx.x;
    if (t < 64) vec[t] = u_table[(size_t)user[b] * 64 + t];
    else        vec[t] = g_pool[b * 64 + (t - 64)];
    __syncthreads();
    float h = b0[t];
#pragma unroll 8
    for (int k = 0; k < 128; k++) h += vec[k] * W0[k * 128 + t];
    red[t] = h * W1[t];
    __syncthreads();
    for (int s = 64; s; s >>= 1) {
        if (t < s) red[t] += red[t + s];
        __syncthreads();
    }
    if (t == 0) {
        float z = red[0] + b1[0];
        out[b] = 1.f / (1.f + expf(-z));
    }
}

// ---------------- launch -----------------------------------------------------
extern "C" void kernel_launch(void* const* d_in, const int* in_sizes, int n_in,
                              void* d_out, int out_size) {
    const int*   user  = (const int*)d_in[0];
    const float* item  = (const float*)d_in[1];
    const int*   eidx  = (const int*)d_in[3];
    const float* u_tab = (const float*)d_in[4];
    const float* i_tab = (const float*)d_in[5];
    const float* W0    = (const float*)d_in[6];
    const float* as0   = (const float*)d_in[7];
    const float* ad0   = (const float*)d_in[8];
    const float* b0    = (const float*)d_in[9];
    const float* W1    = (const float*)d_in[10];
    const float* as1   = (const float*)d_in[11];
    const float* ad1   = (const float*)d_in[12];
    const float* b1    = (const float*)d_in[13];
    const float* lW0   = (const float*)d_in[14];
    const float* lb0   = (const float*)d_in[15];
    const float* lW1   = (const float*)d_in[16];
    const float* lb1   = (const float*)d_in[17];
    float* out = (float*)d_out;

    const int GXP = (NN + 31) / 32;
    const int SCAN_SMEM = NN * (int)sizeof(int);   // 200000 B dynamic smem

    static int scan_attr_set = 0;
    if (!scan_attr_set) {
        cudaFuncSetAttribute(k_scan, cudaFuncAttributeMaxDynamicSharedMemorySize, SCAN_SMEM);
        scan_attr_set = 1;
    }

    // CSR build interleaved with layer-0 GEMM (gemm at position 4 -> gets profiled)
    k_init_deg<<<(NN + 255) / 256, 256>>>();
    k_count<<<(NE + 255) / 256, 256>>>(eidx);
    k_scan<<<1, 1024, SCAN_SMEM>>>();
    k_gemm_mma<<<GXP, 256>>>(i_tab, W0, 0);          // independent of CSR
    k_scatter<<<(ET + 255) / 256, 256>>>(eidx);

    // GAT layer 0 (rest)
    k_prew<<<1, 384>>>(W0, as0, ad0);
    k_attn2<<<(NN + 127) / 128, 128>>>(i_tab, 0);
    k_edge<<<6250, 256>>>(b0, 0);

    // GAT layer 1
    k_gemm_mma<<<GXP, 256>>>(i_tab, W1, 1);
    k_prew<<<1, 384>>>(W1, as1, ad1);
    k_attn2<<<(NN + 127) / 128, 128>>>(i_tab, 1);
    k_edge<<<6250, 256>>>(b1, 1);

    // pooling GEMM + MLP head
    k_transpose<<<dim3((NN + 31) / 32, 2), dim3(32, 8)>>>();
    k_zero_pool<<<(BATCH * D + 255) / 256, 256>>>();
    k_pool_mma<<<dim3(BATCH / 256, PPK), 256>>>(item);
    k_mlp<<<BATCH, 128>>>(user, u_tab, lW0, lb0, lW1, lb1, out);
}